// round 14
// baseline (speedup 1.0000x reference)
#include <cuda_runtime.h>
#include <math.h>
#include <stdint.h>

// Problem dims
#define T_TOK 4096
#define NS    4095        // T-1 steps
#define EDIM  512
#define HDIM  1024
#define G4H   4096        // 4*H
#define NCLS  1221

// Recurrence config
#define NBLK  128         // persistent CTAs (all co-resident on 148 SMs)
#define HPB   8           // H / NBLK h-indices per CTA
#define REC_T 256         // threads per recurrence CTA

// Per-producer release line: h slice (sector 0) + flag (sector 1), 128B.
struct __align__(128) HRel {
    float    h[HPB];      // 32 bytes = 1 sector
    unsigned flag;        // monotonic step counter
    unsigned pad[23];
};

// ---------------- device scratch (no allocations allowed) ----------------
__device__ float g_xs[NS * (2 * EDIM)];             // [4095,1024] concat inputs
__device__ float g_xg[(size_t)NS * G4H];            // [4095,4096] x gate preacts
__device__ float g_hs[(size_t)NS * HDIM];           // [4095,1024] hidden outputs
__device__ HRel  g_hrel[2][NBLK];                   // parity x producer lines
__device__ float g_bias[G4H];                       // b_ih + b_hh

// Acquire load (orders subsequent loads after the flag observation).
__device__ __forceinline__ unsigned ld_acquire(const unsigned* p) {
    unsigned v;
    asm volatile("ld.acquire.gpu.global.u32 %0, [%1];"
                 : "=r"(v) : "l"(p) : "memory");
    return v;
}
// Release store (orders this thread's prior stores before the flag).
__device__ __forceinline__ void st_release(unsigned* p, unsigned v) {
    asm volatile("st.release.gpu.global.u32 [%0], %1;"
                 :: "l"(p), "r"(v) : "memory");
}

// Packed dual-FMA (FFMA2): d = a*b + c on two f32 lanes of a 64-bit reg.
__device__ __forceinline__ unsigned long long ffma2(unsigned long long a,
                                                    unsigned long long b,
                                                    unsigned long long c) {
    unsigned long long d;
    asm("fma.rn.f32x2 %0, %1, %2, %3;" : "=l"(d) : "l"(a), "l"(b), "l"(c));
    return d;
}
__device__ __forceinline__ float f2_lo(unsigned long long v) {
    return __uint_as_float((unsigned)(v & 0xffffffffull));
}
__device__ __forceinline__ float f2_hi(unsigned long long v) {
    return __uint_as_float((unsigned)(v >> 32));
}

// ---------------- kernel 0: embed/concat + init ----------------
__global__ void prep_kernel(const int* __restrict__ x,
                            const float* __restrict__ emb,
                            const float* __restrict__ b_ih,
                            const float* __restrict__ b_hh) {
    int b = blockIdx.x;
    if (b < NS) {
        int tok  = x[b];
        int last = x[NS];
        const float* e0 = emb + (size_t)tok  * EDIM;
        const float* e1 = emb + (size_t)last * EDIM;
        float* dst = g_xs + (size_t)b * (2 * EDIM);
        for (int j = threadIdx.x; j < EDIM; j += blockDim.x) {
            dst[j]        = e0[j];
            dst[EDIM + j] = e1[j];
        }
    } else {
        // init block: bias sum; zero both parity release lines (h + flags)
        for (int j = threadIdx.x; j < G4H; j += blockDim.x)
            g_bias[j] = b_ih[j] + b_hh[j];
        unsigned* hr = (unsigned*)&g_hrel[0][0];
        int nw = 2 * NBLK * (int)(sizeof(HRel) / 4);
        for (int j = threadIdx.x; j < nw; j += blockDim.x)
            hr[j] = 0u;                    // h(0)=0 and flags=0
    }
}

// ---------------- generic SGEMM: C[m,n] = sum_k A[m,k]*B[n,k] + bias[n] ----
// BK=16: each thread loads 2 rows per tile (loader loop), halves barriers.
template <int BM, int BN, int BK, int TM, int TN, int NT>
__global__ void __launch_bounds__(NT)
sgemm_tn(const float* __restrict__ A, const float* __restrict__ B,
         const float* __restrict__ bias, float* __restrict__ C,
         int M, int N, int K) {
    __shared__ float As[BK][BM];
    __shared__ float Bs[BK][BN];

    const int m0 = blockIdx.y * BM;
    const int n0 = blockIdx.x * BN;
    const int tid = threadIdx.x;

    const int arow  = tid / (BK / 4);      // 0..(NT/(BK/4))-1
    const int acol  = (tid % (BK / 4)) * 4;
    const int RSTEP = NT / (BK / 4);       // rows covered per pass
    const int tx = tid % (BN / TN);
    const int ty = tid / (BN / TN);

    float acc[TM][TN];
#pragma unroll
    for (int i = 0; i < TM; i++)
#pragma unroll
        for (int j = 0; j < TN; j++) acc[i][j] = 0.0f;

    for (int k0 = 0; k0 < K; k0 += BK) {
#pragma unroll
        for (int r = arow; r < BM; r += RSTEP) {
            float4 av = make_float4(0.f, 0.f, 0.f, 0.f);
            if (m0 + r < M)
                av = *(const float4*)(A + (size_t)(m0 + r) * K + k0 + acol);
            As[acol + 0][r] = av.x;
            As[acol + 1][r] = av.y;
            As[acol + 2][r] = av.z;
            As[acol + 3][r] = av.w;

            float4 bv = make_float4(0.f, 0.f, 0.f, 0.f);
            if (n0 + r < N)
                bv = *(const float4*)(B + (size_t)(n0 + r) * K + k0 + acol);
            Bs[acol + 0][r] = bv.x;
            Bs[acol + 1][r] = bv.y;
            Bs[acol + 2][r] = bv.z;
            Bs[acol + 3][r] = bv.w;
        }
        __syncthreads();

#pragma unroll
        for (int k = 0; k < BK; k++) {
            float ar[TM], br[TN];
#pragma unroll
            for (int i = 0; i < TM; i++) ar[i] = As[k][ty * TM + i];
#pragma unroll
            for (int j = 0; j < TN; j++) br[j] = Bs[k][tx * TN + j];
#pragma unroll
            for (int i = 0; i < TM; i++)
#pragma unroll
                for (int j = 0; j < TN; j++)
                    acc[i][j] = fmaf(ar[i], br[j], acc[i][j]);
        }
        __syncthreads();
    }

#pragma unroll
    for (int i = 0; i < TM; i++) {
        int m = m0 + ty * TM + i;
        if (m >= M) continue;
#pragma unroll
        for (int j = 0; j < TN; j++) {
            int n = n0 + tx * TN + j;
            if (n < N) C[(size_t)m * N + n] = acc[i][j] + bias[n];
        }
    }
}

// ---------------- persistent LSTM recurrence ----------------
// Fence-free release: lanes 0..7 plain-store h into the producer's parity
// line, __syncwarp (intra-warp memory ordering), lane 0 st.release flag in
// the SAME line. Consumers: even lanes tight-spin acquire on the flag,
// __syncwarp, both lanes __ldcg their float4 from the line.
__global__ void __launch_bounds__(REC_T, 1)
lstm_rec(const float* __restrict__ Whh) {
    __shared__ float4 h4_s[HDIM / 4];     // staged h(t)
    __shared__ float red[2][32];          // warp dot results (parity)
    __shared__ float xg_s[2][32];         // x-gate slice (parity)

    const int b = blockIdx.x;
    const int tid = threadIdx.x;
    const int base = b * HPB;
    const int w = tid >> 5;
    const int l = tid & 31;

    // Weight slice as f32x2: rows r = 4w..4w+3 (gate = r>>3, idx = r&7),
    // lane l holds k-pairs (2(l+32i), 2(l+32i)+1), i = 0..15.
    unsigned long long wreg[4][16];
#pragma unroll
    for (int rr = 0; rr < 4; rr++) {
        int r = 4 * w + rr;
        int grow = (r >> 3) * HDIM + base + (r & 7);
        const unsigned long long* wp =
            (const unsigned long long*)(Whh + (size_t)grow * HDIM);
#pragma unroll
        for (int i = 0; i < 16; i++) wreg[rr][i] = wp[l + 32 * i];
    }

    float c_reg = 0.0f;                   // cell state (warp 0, lanes 0..7)

    // prefetch xg(0) into a register (warp 7)
    float xg_next = 0.0f;
    const int xr = tid - 224;             // 0..31 for warp 7
    if (tid >= 224)
        xg_next = __ldcg(&g_xg[(size_t)0 * G4H + (xr >> 3) * HDIM + base + (xr & 7)]);

    const int q = tid >> 1;               // this thread's producer CTA

    for (int t = 0; t < NS; t++) {
        const int p = t & 1;

        // commit prefetched xg(t); issue prefetch of xg(t+1)
        if (tid >= 224) {
            xg_s[p][xr] = xg_next;
            if (t + 1 < NS)
                xg_next = __ldcg(&g_xg[(size_t)(t + 1) * G4H +
                                       (xr >> 3) * HDIM + base + (xr & 7)]);
        }

        // even lanes acquire-spin on producer q's flag in parity line t&1;
        // odd lanes inherit ordering via __syncwarp (intra-warp mem barrier)
        HRel* line = &g_hrel[p][q];
        if (t > 0) {
            if ((tid & 1) == 0) {
                while (ld_acquire(&line->flag) < (unsigned)t) { }
            }
            __syncwarp();
        }
        // load my float4 (lo for even lane, hi for odd) — L2, not L1
        h4_s[tid] = __ldcg((const float4*)&line->h[(tid & 1) * 4]);
        __syncthreads();                  // barrier #1: h_s fully staged

        // 4 rows per warp, packed f32x2 dot products over H=1024
        const unsigned long long* h2 = (const unsigned long long*)h4_s;
        unsigned long long a0 = 0, a1 = 0, a2 = 0, a3 = 0;
#pragma unroll
        for (int i = 0; i < 16; i++) {
            unsigned long long hp = h2[l + 32 * i];
            a0 = ffma2(wreg[0][i], hp, a0);
            a1 = ffma2(wreg[1][i], hp, a1);
            a2 = ffma2(wreg[2][i], hp, a2);
            a3 = ffma2(wreg[3][i], hp, a3);
        }
        float s0 = f2_lo(a0) + f2_hi(a0);
        float s1 = f2_lo(a1) + f2_hi(a1);
        float s2 = f2_lo(a2) + f2_hi(a2);
        float s3 = f2_lo(a3) + f2_hi(a3);
#pragma unroll
        for (int off = 16; off; off >>= 1) {
            s0 += __shfl_down_sync(0xffffffffu, s0, off);
            s1 += __shfl_down_sync(0xffffffffu, s1, off);
            s2 += __shfl_down_sync(0xffffffffu, s2, off);
            s3 += __shfl_down_sync(0xffffffffu, s3, off);
        }
        if (l == 0) {
            red[p][4 * w + 0] = s0;
            red[p][4 * w + 1] = s1;
            red[p][4 * w + 2] = s2;
            red[p][4 * w + 3] = s3;
        }

        // warps 1-7: arrive and run ahead; warp 0: epilogue + release.
        if (w != 0) {
            asm volatile("bar.arrive 3, %0;" :: "r"(REC_T) : "memory");
        } else {
            asm volatile("bar.sync 3, %0;" :: "r"(REC_T) : "memory");

            float pre = red[p][l] + xg_s[p][l];
            float act = ((l >> 3) == 2) ? tanhf(pre)
                                        : 1.0f / (1.0f + expf(-pre));
            int j = l & 7;
            float iv = __shfl_sync(0xffffffffu, act, j);
            float fv = __shfl_sync(0xffffffffu, act, j + 8);
            float gv = __shfl_sync(0xffffffffu, act, j + 16);
            float ov = __shfl_sync(0xffffffffu, act, j + 24);
            float hh = 0.0f;
            HRel* out = &g_hrel[(t + 1) & 1][b];
            if (l < 8) {
                c_reg = fv * c_reg + iv * gv;
                hh = ov * tanhf(c_reg);
                out->h[j] = hh;           // plain store into release line
            }
            __syncwarp();                 // intra-warp ordering of h stores
            if (l == 0)
                st_release(&out->flag, (unsigned)(t + 1));  // fence-free
            if (l < 8)                    // history store off critical path
                g_hs[(size_t)t * HDIM + base + j] = hh;
        }
        // red/xg_s parity-buffered; parity-line overwrite safety: a producer
        // reaches step t's release only after all flags >= t, and any CTA's
        // flag >= t implies its reads of parity (t-1)&1 completed.
    }
}

// ---------------- launch ----------------
extern "C" void kernel_launch(void* const* d_in, const int* in_sizes, int n_in,
                              void* d_out, int out_size) {
    const int*   x     = (const int*)d_in[0];
    const float* emb   = (const float*)d_in[1];
    const float* W_ih  = (const float*)d_in[2];
    const float* W_hh  = (const float*)d_in[3];
    const float* b_ih  = (const float*)d_in[4];
    const float* b_hh  = (const float*)d_in[5];
    const float* W_out = (const float*)d_in[6];
    const float* b_out = (const float*)d_in[7];
    float* out = (float*)d_out;

    float *p_xs, *p_xg, *p_hs, *p_bias;
    cudaGetSymbolAddress((void**)&p_xs, g_xs);
    cudaGetSymbolAddress((void**)&p_xg, g_xg);
    cudaGetSymbolAddress((void**)&p_hs, g_hs);
    cudaGetSymbolAddress((void**)&p_bias, g_bias);

    // 0) embed + concat + init release lines/bias
    prep_kernel<<<NS + 1, 256>>>(x, emb, b_ih, b_hh);

    // 1) x_gates = xs @ W_ih^T + (b_ih+b_hh)   [4095 x 4096]
    {
        dim3 grid(G4H / 128, (NS + 127) / 128);
        sgemm_tn<128, 128, 16, 8, 8, 256><<<grid, 256>>>(
            p_xs, W_ih, p_bias, p_xg, NS, G4H, 2 * EDIM);
    }

    // 2) serial LSTM scan (persistent cooperative kernel)
    lstm_rec<<<NBLK, REC_T>>>(W_hh);

    // 3) out = hs @ W_out^T + b_out   [4095 x 1221]
    {
        dim3 grid((NCLS + 127) / 128, (NS + 127) / 128);
        sgemm_tn<128, 128, 16, 8, 8, 256><<<grid, 256>>>(
            p_hs, W_out, b_out, out, NS, NCLS, HDIM);
    }
}

// round 15
// speedup vs baseline: 1.0186x; 1.0186x over previous
#include <cuda_runtime.h>
#include <math.h>
#include <stdint.h>

// Problem dims
#define T_TOK 4096
#define NS    4095        // T-1 steps
#define EDIM  512
#define HDIM  1024
#define G4H   4096        // 4*H
#define NCLS  1221

// Recurrence config
#define NBLK  128         // persistent CTAs (all co-resident on 148 SMs)
#define HPB   8           // H / NBLK h-indices per CTA
#define REC_T 256         // threads per recurrence CTA

// Per-producer release line: h slice (sector 0) + flag (sector 1), 128B.
struct __align__(128) HRel {
    float    h[HPB];      // 32 bytes = 1 sector
    unsigned flag;        // monotonic step counter
    unsigned pad[23];
};

// ---------------- device scratch (no allocations allowed) ----------------
__device__ float g_xs[NS * (2 * EDIM)];             // [4095,1024] concat inputs
__device__ float g_xg[(size_t)NS * G4H];            // [4095,4096] x gate preacts
__device__ float g_hs[(size_t)NS * HDIM];           // [4095,1024] hidden outputs
__device__ HRel  g_hrel[2][NBLK];                   // parity x producer lines
__device__ float g_bias[G4H];                       // b_ih + b_hh

// Acquire load (orders subsequent loads after the flag observation).
__device__ __forceinline__ unsigned ld_acquire(const unsigned* p) {
    unsigned v;
    asm volatile("ld.acquire.gpu.global.u32 %0, [%1];"
                 : "=r"(v) : "l"(p) : "memory");
    return v;
}
// Release store (orders this thread's prior stores before the flag).
__device__ __forceinline__ void st_release(unsigned* p, unsigned v) {
    asm volatile("st.release.gpu.global.u32 [%0], %1;"
                 :: "l"(p), "r"(v) : "memory");
}

// Packed dual-FMA (FFMA2): d = a*b + c on two f32 lanes of a 64-bit reg.
__device__ __forceinline__ unsigned long long ffma2(unsigned long long a,
                                                    unsigned long long b,
                                                    unsigned long long c) {
    unsigned long long d;
    asm("fma.rn.f32x2 %0, %1, %2, %3;" : "=l"(d) : "l"(a), "l"(b), "l"(c));
    return d;
}
__device__ __forceinline__ float f2_lo(unsigned long long v) {
    return __uint_as_float((unsigned)(v & 0xffffffffull));
}
__device__ __forceinline__ float f2_hi(unsigned long long v) {
    return __uint_as_float((unsigned)(v >> 32));
}

// ---------------- kernel 0: embed/concat + init ----------------
__global__ void prep_kernel(const int* __restrict__ x,
                            const float* __restrict__ emb,
                            const float* __restrict__ b_ih,
                            const float* __restrict__ b_hh) {
    int b = blockIdx.x;
    if (b < NS) {
        int tok  = x[b];
        int last = x[NS];
        const float* e0 = emb + (size_t)tok  * EDIM;
        const float* e1 = emb + (size_t)last * EDIM;
        float* dst = g_xs + (size_t)b * (2 * EDIM);
        for (int j = threadIdx.x; j < EDIM; j += blockDim.x) {
            dst[j]        = e0[j];
            dst[EDIM + j] = e1[j];
        }
    } else {
        // init block: bias sum; zero both parity release lines (h + flags)
        for (int j = threadIdx.x; j < G4H; j += blockDim.x)
            g_bias[j] = b_ih[j] + b_hh[j];
        unsigned* hr = (unsigned*)&g_hrel[0][0];
        int nw = 2 * NBLK * (int)(sizeof(HRel) / 4);
        for (int j = threadIdx.x; j < nw; j += blockDim.x)
            hr[j] = 0u;                    // h(0)=0 and flags=0
    }
}

// ------- double-buffered SGEMM: C[m,n] = sum_k A[m,k]*B[n,k] + bias[n] ----
// Prefetch tile k+1 (global->regs) during compute of tile k; store to the
// alternate smem buffer; one __syncthreads per K-tile.
template <int BM, int BN, int BK, int TM, int TN, int NT>
__global__ void __launch_bounds__(NT)
sgemm_db(const float* __restrict__ A, const float* __restrict__ B,
         const float* __restrict__ bias, float* __restrict__ C,
         int M, int N, int K) {
    __shared__ float As[2][BK][BM];
    __shared__ float Bs[2][BK][BN];

    const int m0 = blockIdx.y * BM;
    const int n0 = blockIdx.x * BN;
    const int tid = threadIdx.x;

    const int arow  = tid / (BK / 4);      // 0..NT/(BK/4)-1
    const int acol  = (tid % (BK / 4)) * 4;
    constexpr int RSTEP = NT / (BK / 4);   // rows per pass (64)
    constexpr int NLOAD = BM / RSTEP;      // passes per tile (2)
    const int tx = tid % (BN / TN);
    const int ty = tid / (BN / TN);

    float4 pa[NLOAD], pb[NLOAD];
    const float4 fz = make_float4(0.f, 0.f, 0.f, 0.f);

    // prefetch tile 0
#pragma unroll
    for (int i = 0; i < NLOAD; i++) {
        int r = arow + i * RSTEP;
        pa[i] = (m0 + r < M) ? *(const float4*)(A + (size_t)(m0 + r) * K + acol) : fz;
        pb[i] = (n0 + r < N) ? *(const float4*)(B + (size_t)(n0 + r) * K + acol) : fz;
    }
#pragma unroll
    for (int i = 0; i < NLOAD; i++) {
        int r = arow + i * RSTEP;
        As[0][acol + 0][r] = pa[i].x; As[0][acol + 1][r] = pa[i].y;
        As[0][acol + 2][r] = pa[i].z; As[0][acol + 3][r] = pa[i].w;
        Bs[0][acol + 0][r] = pb[i].x; Bs[0][acol + 1][r] = pb[i].y;
        Bs[0][acol + 2][r] = pb[i].z; Bs[0][acol + 3][r] = pb[i].w;
    }
    __syncthreads();

    float acc[TM][TN];
#pragma unroll
    for (int i = 0; i < TM; i++)
#pragma unroll
        for (int j = 0; j < TN; j++) acc[i][j] = 0.0f;

    const int nk = K / BK;
    for (int kt = 0; kt < nk; kt++) {
        const int cur = kt & 1;
        const int nxt = cur ^ 1;

        // issue next tile's global loads early (latency hidden by compute)
        if (kt + 1 < nk) {
            int k0 = (kt + 1) * BK;
#pragma unroll
            for (int i = 0; i < NLOAD; i++) {
                int r = arow + i * RSTEP;
                pa[i] = (m0 + r < M) ? *(const float4*)(A + (size_t)(m0 + r) * K + k0 + acol) : fz;
                pb[i] = (n0 + r < N) ? *(const float4*)(B + (size_t)(n0 + r) * K + k0 + acol) : fz;
            }
        }

#pragma unroll
        for (int k = 0; k < BK; k++) {
            float ar[TM], br[TN];
#pragma unroll
            for (int i = 0; i < TM; i++) ar[i] = As[cur][k][ty * TM + i];
#pragma unroll
            for (int j = 0; j < TN; j++) br[j] = Bs[cur][k][tx * TN + j];
#pragma unroll
            for (int i = 0; i < TM; i++)
#pragma unroll
                for (int j = 0; j < TN; j++)
                    acc[i][j] = fmaf(ar[i], br[j], acc[i][j]);
        }

        if (kt + 1 < nk) {
#pragma unroll
            for (int i = 0; i < NLOAD; i++) {
                int r = arow + i * RSTEP;
                As[nxt][acol + 0][r] = pa[i].x; As[nxt][acol + 1][r] = pa[i].y;
                As[nxt][acol + 2][r] = pa[i].z; As[nxt][acol + 3][r] = pa[i].w;
                Bs[nxt][acol + 0][r] = pb[i].x; Bs[nxt][acol + 1][r] = pb[i].y;
                Bs[nxt][acol + 2][r] = pb[i].z; Bs[nxt][acol + 3][r] = pb[i].w;
            }
            __syncthreads();
        }
    }

#pragma unroll
    for (int i = 0; i < TM; i++) {
        int m = m0 + ty * TM + i;
        if (m >= M) continue;
#pragma unroll
        for (int j = 0; j < TN; j++) {
            int n = n0 + tx * TN + j;
            if (n < N) C[(size_t)m * N + n] = acc[i][j] + bias[n];
        }
    }
}

// ---------------- persistent LSTM recurrence ----------------
// Packed-line fence-free release (R14) + failed-probe backoff (R13-proven):
// lanes 0..7 plain-store h into the producer's parity line, __syncwarp,
// lane 0 st.release flag in the SAME line. Consumers: even lanes acquire-
// poll with __nanosleep backoff only after a miss, __syncwarp, both lanes
// __ldcg their float4 from the line.
__global__ void __launch_bounds__(REC_T, 1)
lstm_rec(const float* __restrict__ Whh) {
    __shared__ float4 h4_s[HDIM / 4];     // staged h(t)
    __shared__ float red[2][32];          // warp dot results (parity)
    __shared__ float xg_s[2][32];         // x-gate slice (parity)

    const int b = blockIdx.x;
    const int tid = threadIdx.x;
    const int base = b * HPB;
    const int w = tid >> 5;
    const int l = tid & 31;

    // Weight slice as f32x2: rows r = 4w..4w+3 (gate = r>>3, idx = r&7),
    // lane l holds k-pairs (2(l+32i), 2(l+32i)+1), i = 0..15.
    unsigned long long wreg[4][16];
#pragma unroll
    for (int rr = 0; rr < 4; rr++) {
        int r = 4 * w + rr;
        int grow = (r >> 3) * HDIM + base + (r & 7);
        const unsigned long long* wp =
            (const unsigned long long*)(Whh + (size_t)grow * HDIM);
#pragma unroll
        for (int i = 0; i < 16; i++) wreg[rr][i] = wp[l + 32 * i];
    }

    float c_reg = 0.0f;                   // cell state (warp 0, lanes 0..7)

    // prefetch xg(0) into a register (warp 7)
    float xg_next = 0.0f;
    const int xr = tid - 224;             // 0..31 for warp 7
    if (tid >= 224)
        xg_next = __ldcg(&g_xg[(size_t)0 * G4H + (xr >> 3) * HDIM + base + (xr & 7)]);

    const int q = tid >> 1;               // this thread's producer CTA

    for (int t = 0; t < NS; t++) {
        const int p = t & 1;

        // commit prefetched xg(t); issue prefetch of xg(t+1)
        if (tid >= 224) {
            xg_s[p][xr] = xg_next;
            if (t + 1 < NS)
                xg_next = __ldcg(&g_xg[(size_t)(t + 1) * G4H +
                                       (xr >> 3) * HDIM + base + (xr & 7)]);
        }

        // even lanes acquire-poll producer q's flag (backoff after a miss);
        // odd lanes inherit ordering via __syncwarp.
        HRel* line = &g_hrel[p][q];
        if (t > 0) {
            if ((tid & 1) == 0) {
                if (ld_acquire(&line->flag) < (unsigned)t) {
                    do {
                        __nanosleep(100);
                    } while (ld_acquire(&line->flag) < (unsigned)t);
                }
            }
            __syncwarp();
        }
        // load my float4 (lo for even lane, hi for odd) — L2, not L1
        h4_s[tid] = __ldcg((const float4*)&line->h[(tid & 1) * 4]);
        __syncthreads();                  // barrier #1: h_s fully staged

        // 4 rows per warp, packed f32x2 dot products over H=1024
        const unsigned long long* h2 = (const unsigned long long*)h4_s;
        unsigned long long a0 = 0, a1 = 0, a2 = 0, a3 = 0;
#pragma unroll
        for (int i = 0; i < 16; i++) {
            unsigned long long hp = h2[l + 32 * i];
            a0 = ffma2(wreg[0][i], hp, a0);
            a1 = ffma2(wreg[1][i], hp, a1);
            a2 = ffma2(wreg[2][i], hp, a2);
            a3 = ffma2(wreg[3][i], hp, a3);
        }
        float s0 = f2_lo(a0) + f2_hi(a0);
        float s1 = f2_lo(a1) + f2_hi(a1);
        float s2 = f2_lo(a2) + f2_hi(a2);
        float s3 = f2_lo(a3) + f2_hi(a3);
#pragma unroll
        for (int off = 16; off; off >>= 1) {
            s0 += __shfl_down_sync(0xffffffffu, s0, off);
            s1 += __shfl_down_sync(0xffffffffu, s1, off);
            s2 += __shfl_down_sync(0xffffffffu, s2, off);
            s3 += __shfl_down_sync(0xffffffffu, s3, off);
        }
        if (l == 0) {
            red[p][4 * w + 0] = s0;
            red[p][4 * w + 1] = s1;
            red[p][4 * w + 2] = s2;
            red[p][4 * w + 3] = s3;
        }

        // warps 1-7: arrive and run ahead; warp 0: epilogue + release.
        if (w != 0) {
            asm volatile("bar.arrive 3, %0;" :: "r"(REC_T) : "memory");
        } else {
            asm volatile("bar.sync 3, %0;" :: "r"(REC_T) : "memory");

            float pre = red[p][l] + xg_s[p][l];
            float act = ((l >> 3) == 2) ? tanhf(pre)
                                        : 1.0f / (1.0f + expf(-pre));
            int j = l & 7;
            float iv = __shfl_sync(0xffffffffu, act, j);
            float fv = __shfl_sync(0xffffffffu, act, j + 8);
            float gv = __shfl_sync(0xffffffffu, act, j + 16);
            float ov = __shfl_sync(0xffffffffu, act, j + 24);
            float hh = 0.0f;
            HRel* out = &g_hrel[(t + 1) & 1][b];
            if (l < 8) {
                c_reg = fv * c_reg + iv * gv;
                hh = ov * tanhf(c_reg);
                out->h[j] = hh;           // plain store into release line
            }
            __syncwarp();                 // intra-warp ordering of h stores
            if (l == 0)
                st_release(&out->flag, (unsigned)(t + 1));  // fence-free
            if (l < 8)                    // history store off critical path
                g_hs[(size_t)t * HDIM + base + j] = hh;
        }
        // red/xg_s parity-buffered; parity-line overwrite safety: a producer
        // reaches step t's release only after all flags >= t, and any CTA's
        // flag >= t implies its reads of parity (t-1)&1 completed.
    }
}

// ---------------- launch ----------------
extern "C" void kernel_launch(void* const* d_in, const int* in_sizes, int n_in,
                              void* d_out, int out_size) {
    const int*   x     = (const int*)d_in[0];
    const float* emb   = (const float*)d_in[1];
    const float* W_ih  = (const float*)d_in[2];
    const float* W_hh  = (const float*)d_in[3];
    const float* b_ih  = (const float*)d_in[4];
    const float* b_hh  = (const float*)d_in[5];
    const float* W_out = (const float*)d_in[6];
    const float* b_out = (const float*)d_in[7];
    float* out = (float*)d_out;

    float *p_xs, *p_xg, *p_hs, *p_bias;
    cudaGetSymbolAddress((void**)&p_xs, g_xs);
    cudaGetSymbolAddress((void**)&p_xg, g_xg);
    cudaGetSymbolAddress((void**)&p_hs, g_hs);
    cudaGetSymbolAddress((void**)&p_bias, g_bias);

    // 0) embed + concat + init release lines/bias
    prep_kernel<<<NS + 1, 256>>>(x, emb, b_ih, b_hh);

    // 1) x_gates = xs @ W_ih^T + (b_ih+b_hh)   [4095 x 4096]
    {
        dim3 grid(G4H / 128, (NS + 127) / 128);
        sgemm_db<128, 128, 16, 8, 8, 256><<<grid, 256>>>(
            p_xs, W_ih, p_bias, p_xg, NS, G4H, 2 * EDIM);
    }

    // 2) serial LSTM scan (persistent cooperative kernel)
    lstm_rec<<<NBLK, REC_T>>>(W_hh);

    // 3) out = hs @ W_out^T + b_out   [4095 x 1221]
    {
        dim3 grid((NCLS + 127) / 128, (NS + 127) / 128);
        sgemm_db<128, 128, 16, 8, 8, 256><<<grid, 256>>>(
            p_hs, W_out, b_out, out, NS, NCLS, HDIM);
    }
}